// round 15
// baseline (speedup 1.0000x reference)
#include <cuda_runtime.h>
#include <cuda_bf16.h>
#include <cuda_fp16.h>
#include <math.h>
#include <stdint.h>

// Shapes (fixed)
#define BB 2
#define TT 2048
#define DD 1024
#define HH 16
#define DH 64
#define MM (BB*TT)   // 4096
#define BH (BB*HH)   // 32

// ---------------------------------------------------------------------------
// Scratch (no cudaMalloc allowed)
// ---------------------------------------------------------------------------
__device__ __nv_bfloat16 g_A2 [MM*2*DD];      // x split [rows][hi1024|lo1024]
__device__ __half        g_Ah [MM*DD];        // x plain f16 (for V gemm)
__device__ __half        g_Oh [MM*DD];        // attention output f16
__device__ __nv_bfloat16 g_WQ2[DD*2*DD];      // folded Wq split
__device__ __nv_bfloat16 g_WK2[DD*2*DD];      // folded Wk split
__device__ __half        g_WVh[DD*DD];        // Wv f16
__device__ __half        g_WOh[DD*DD];        // Wo f16
__device__ __nv_bfloat16 g_Qs[BH*TT*128];     // [bh][t][hi64|lo64], Q pre-scaled
__device__ __nv_bfloat16 g_Ks[BH*TT*128];     // [bh][t][hi64|lo64]
__device__ __half        g_Vt[BH*DH*TT];      // [bh][d][s]  (f16, transposed)

// ---------------------------------------------------------------------------
// PTX helpers (sm_80-level only — ptxas targets plain sm_103, no tcgen05/TMA)
// ---------------------------------------------------------------------------
__device__ __forceinline__ uint32_t smem_u32(const void* p) {
    uint32_t a;
    asm("{ .reg .u64 t; cvta.to.shared.u64 t, %1; cvt.u32.u64 %0, t; }" : "=r"(a) : "l"(p));
    return a;
}
__device__ __forceinline__ void cp_async16(uint32_t dst, const void* src) {
    asm volatile("cp.async.cg.shared.global [%0], [%1], 16;\n" :: "r"(dst), "l"(src));
}
#define CP_COMMIT() asm volatile("cp.async.commit_group;\n" ::: "memory")
#define CP_WAIT0()  asm volatile("cp.async.wait_group 0;\n" ::: "memory")
#define CP_WAIT1()  asm volatile("cp.async.wait_group 1;\n" ::: "memory")

__device__ __forceinline__ void ldsm4(uint32_t &r0, uint32_t &r1, uint32_t &r2, uint32_t &r3,
                                      uint32_t addr) {
    asm volatile("ldmatrix.sync.aligned.m8n8.x4.shared.b16 {%0,%1,%2,%3}, [%4];"
                 : "=r"(r0), "=r"(r1), "=r"(r2), "=r"(r3) : "r"(addr));
}
__device__ __forceinline__ void mma_bf16(float* c, const uint32_t* a, const uint32_t* b) {
    asm volatile("mma.sync.aligned.m16n8k16.row.col.f32.bf16.bf16.f32 "
                 "{%0,%1,%2,%3}, {%4,%5,%6,%7}, {%8,%9}, {%0,%1,%2,%3};"
                 : "+f"(c[0]), "+f"(c[1]), "+f"(c[2]), "+f"(c[3])
                 : "r"(a[0]), "r"(a[1]), "r"(a[2]), "r"(a[3]), "r"(b[0]), "r"(b[1]));
}
__device__ __forceinline__ void mma_f16(float* c, const uint32_t* a, const uint32_t* b) {
    asm volatile("mma.sync.aligned.m16n8k16.row.col.f32.f16.f16.f32 "
                 "{%0,%1,%2,%3}, {%4,%5,%6,%7}, {%8,%9}, {%0,%1,%2,%3};"
                 : "+f"(c[0]), "+f"(c[1]), "+f"(c[2]), "+f"(c[3])
                 : "r"(a[0]), "r"(a[1]), "r"(a[2]), "r"(a[3]), "r"(b[0]), "r"(b[1]));
}
__device__ __forceinline__ float ex2f(float x) {
    float r; asm("ex2.approx.ftz.f32 %0, %1;" : "=f"(r) : "f"(x)); return r;
}
__device__ __forceinline__ uint32_t ex2_h2(uint32_t x) {
    uint32_t r; asm("ex2.approx.f16x2 %0, %1;" : "=r"(r) : "r"(x)); return r;
}
__device__ __forceinline__ uint32_t f2h2u(float a, float b) {
    __half2 h = __floats2half2_rn(a, b);
    return *reinterpret_cast<uint32_t*>(&h);
}
__device__ __forceinline__ float2 h2u2f2(uint32_t u) {
    __half2 h = *reinterpret_cast<__half2*>(&u);
    return __half22float2(h);
}
__device__ __forceinline__ uint32_t pack_bf16(float a, float b) {
    __nv_bfloat162 h = __floats2bfloat162_rn(a, b);
    return *reinterpret_cast<uint32_t*>(&h);
}
__device__ __forceinline__ void split2(float v0, float v1, uint32_t &hi, uint32_t &lo) {
    __nv_bfloat16 h0 = __float2bfloat16(v0);
    __nv_bfloat16 h1 = __float2bfloat16(v1);
    float l0 = v0 - __bfloat162float(h0);
    float l1 = v1 - __bfloat162float(h1);
    uint32_t u0 = (uint32_t)*reinterpret_cast<uint16_t*>(&h0);
    uint32_t u1 = (uint32_t)*reinterpret_cast<uint16_t*>(&h1);
    hi = u0 | (u1 << 16);
    lo = pack_bf16(l0, l1);
}

// 64B-row swizzle: 16B-chunk c4 XOR bits (r>>1)&3 -> conflict-free ldsm
#define SWZ64(r, c4) ((uint32_t)((r)*64 + ((((c4) ^ (((r) >> 1) & 3)) & 3) << 4)))

// ---------------------------------------------------------------------------
// prep: flat grid. blocks [0, 16384): x -> bf16 split + f16 copy.
//       blocks [16384, 16640): weight fold/split (weff, 256 blocks).
// ---------------------------------------------------------------------------
#define CVT_BLKS (MM*DD/256)     // 16384

__global__ __launch_bounds__(256)
void prep_kernel(const float* __restrict__ x,
                 const float* __restrict__ Wq, const float* __restrict__ Wk,
                 const float* __restrict__ Wv, const float* __restrict__ Wo,
                 const float* __restrict__ Sq, const float* __restrict__ Sk)
{
    __shared__ float s_s[DH*DH];
    const int blk = blockIdx.x;
    if (blk < CVT_BLKS) {
        int i = blk * 256 + threadIdx.x;
        int r = i >> 10, c = i & 1023;
        float v = x[i];
        __nv_bfloat16 hi = __float2bfloat16(v);
        float lof = v - __bfloat162float(hi);
        g_A2[(size_t)r*2048 + c] = hi;
        g_A2[(size_t)r*2048 + 1024 + c] = __float2bfloat16(lof);
        g_Ah[i] = __float2half_rn(v);
        return;
    }
    const int zz = blk - CVT_BLKS;        // 0..255
    const int z  = zz >> 6;               // 0..3
    const int h  = (zz >> 2) & 15;
    const int d  = (zz & 3) * 256 + threadIdx.x;

    if (z < 2) {
        const float* __restrict__ W = z ? Wk : Wq;
        const float* __restrict__ S = z ? Sk : Sq;
        __nv_bfloat16* __restrict__ outp = z ? g_WK2 : g_WQ2;

        for (int i = threadIdx.x; i < DH*DH; i += 256) s_s[i] = S[h*DH*DH + i];
        __syncthreads();

        float acc[DH];
#pragma unroll
        for (int e = 0; e < DH; e++) acc[e] = 0.f;
        for (int c = 0; c < DH; c++) {
            const float w = W[(h*DH + c)*DD + d];
#pragma unroll
            for (int e = 0; e < DH; e++) acc[e] += w * s_s[c*DH + e];
        }
#pragma unroll
        for (int e = 0; e < DH; e++) {
            float v = acc[e];
            __nv_bfloat16 hi = __float2bfloat16(v);
            float lo = v - __bfloat162float(hi);
            outp[(size_t)(h*DH + e)*2048 + d] = hi;
            outp[(size_t)(h*DH + e)*2048 + 1024 + d] = __float2bfloat16(lo);
        }
    } else {
        const float* __restrict__ W = (z == 2) ? Wv : Wo;
        __half* __restrict__ outp = (z == 2) ? g_WVh : g_WOh;
        for (int c = 0; c < DH; c++) {
            const int row = h*DH + c;
            outp[(size_t)row*DD + d] = __float2half_rn(W[(size_t)row*DD + d]);
        }
    }
}

// ---------------------------------------------------------------------------
// QK GEMM (3-term bf16), 128-thread CTA (4 warps, 1/SMSP), 4 CTAs/SM.
// Tile 128x64, BK=32, 2 stages. grid (32, 32): x>>4 = 0 -> Q, 1 -> K.
// (unchanged from R14)
// ---------------------------------------------------------------------------
#define Q4_AARR  8192
#define Q4_BARR  4096
#define Q4_STAGE (2*Q4_AARR + 2*Q4_BARR) // 24576
#define Q4_NST   2
#define Q4_SMEM  (Q4_NST*Q4_STAGE)       // 49152

__global__ __launch_bounds__(128, 4)
void gemm_qk_kernel(const __nv_bfloat16* __restrict__ A2,
                    const __nv_bfloat16* __restrict__ Bq,
                    const __nv_bfloat16* __restrict__ Bk, float qscale)
{
    extern __shared__ char smraw[];
    const uint32_t sbase = smem_u32(smraw);
    const int tid = threadIdx.x;
    const int wid = tid >> 5, lane = tid & 31;
    const int warp_m = wid >> 1, warp_n = wid & 1;
    const int m0 = blockIdx.y * 128;
    const int nb = blockIdx.x >> 4;                     // 0=Q, 1=K
    const int n0 = (blockIdx.x & 15) * 64;
    const __nv_bfloat16* __restrict__ B2 = nb ? Bk : Bq;

    float acc[4][4][4];
#pragma unroll
    for (int a = 0; a < 4; a++)
#pragma unroll
        for (int b = 0; b < 4; b++)
#pragma unroll
            for (int c = 0; c < 4; c++) acc[a][b][c] = 0.f;

    auto LOAD = [&](int it) {
        const uint32_t st = sbase + (it & 1) * Q4_STAGE;
        const char* gA = (const char*)A2 + (size_t)m0*4096 + it*64;
        const char* gB = (const char*)B2 + (size_t)n0*4096 + it*64;
#pragma unroll
        for (int i = 0; i < 4; i++) {
            int u = tid + i*128;
            int r = u >> 2, c4 = u & 3;
            const uint32_t so = SWZ64(r, c4);
            const size_t go = (size_t)r*4096 + c4*16;
            cp_async16(st           + so, gA + go);
            cp_async16(st + Q4_AARR + so, gA + 2048 + go);
        }
#pragma unroll
        for (int i = 0; i < 2; i++) {
            int u = tid + i*128;
            int r = u >> 2, c4 = u & 3;
            const uint32_t so = SWZ64(r, c4);
            const size_t go = (size_t)r*4096 + c4*16;
            cp_async16(st + 2*Q4_AARR           + so, gB + go);
            cp_async16(st + 2*Q4_AARR + Q4_BARR + so, gB + 2048 + go);
        }
    };

    LOAD(0); CP_COMMIT();

    const int NIT = 32;
    for (int it = 0; it < NIT; it++) {
        CP_WAIT0();
        __syncthreads();
        if (it + 1 < NIT) LOAD(it + 1);
        CP_COMMIT();
        const uint32_t st = sbase + (it & 1) * Q4_STAGE;
#pragma unroll
        for (int j = 0; j < 2; j++) {
            const int c4 = j*2 + (lane >> 4);
            uint32_t ah[4][4], al[4][4];
#pragma unroll
            for (int mf = 0; mf < 4; mf++) {
                const int r = warp_m*64 + mf*16 + (lane & 15);
                ldsm4(ah[mf][0], ah[mf][1], ah[mf][2], ah[mf][3], st + SWZ64(r, c4));
                ldsm4(al[mf][0], al[mf][1], al[mf][2], al[mf][3], st + Q4_AARR + SWZ64(r, c4));
            }
#pragma unroll
            for (int nf2 = 0; nf2 < 2; nf2++) {
                const int rB = warp_n*32 + nf2*16 + (lane & 15);
                uint32_t r0, r1, r2, r3;
                ldsm4(r0, r1, r2, r3, st + 2*Q4_AARR + SWZ64(rB, c4));     // B hi
                {
                    uint32_t b0[2] = {r0, r2}, b1[2] = {r1, r3};
#pragma unroll
                    for (int mf = 0; mf < 4; mf++) {
                        mma_bf16(acc[mf][2*nf2  ], ah[mf], b0);
                        mma_bf16(acc[mf][2*nf2  ], al[mf], b0);
                        mma_bf16(acc[mf][2*nf2+1], ah[mf], b1);
                        mma_bf16(acc[mf][2*nf2+1], al[mf], b1);
                    }
                }
                ldsm4(r0, r1, r2, r3, st + 2*Q4_AARR + Q4_BARR + SWZ64(rB, c4));  // B lo
                {
                    uint32_t b0[2] = {r0, r2}, b1[2] = {r1, r3};
#pragma unroll
                    for (int mf = 0; mf < 4; mf++) {
                        mma_bf16(acc[mf][2*nf2  ], ah[mf], b0);
                        mma_bf16(acc[mf][2*nf2+1], ah[mf], b1);
                    }
                }
            }
        }
    }

    const int g = lane >> 2, t = lane & 3;
    __nv_bfloat16* dst = (nb == 0) ? g_Qs : g_Ks;
    const float sc = (nb == 0) ? qscale : 1.0f;
#pragma unroll
    for (int mf = 0; mf < 4; mf++) {
        const int row0 = m0 + warp_m*64 + mf*16 + g;
#pragma unroll
        for (int nf = 0; nf < 4; nf++) {
            const int col = n0 + warp_n*32 + nf*8 + t*2;
            const int h = col >> 6, e = col & 63;
#pragma unroll
            for (int rr = 0; rr < 2; rr++) {
                const int row = row0 + rr*8;
                const int b = row >> 11, tq = row & 2047;
                const size_t base = ((size_t)(b*HH + h)*TT + tq) << 7;
                uint32_t hi, lo;
                split2(acc[mf][nf][rr*2] * sc, acc[mf][nf][rr*2+1] * sc, hi, lo);
                *(uint32_t*)&dst[base + e]      = hi;
                *(uint32_t*)&dst[base + 64 + e] = lo;
            }
        }
    }
}

// ---------------------------------------------------------------------------
// 1-term f16 GEMM, 128-thread CTA (4 warps), 4 CTAs/SM. Tile 128x64, BK=32,
// 3 stages. grid (16, 32). MODE 0: fp32 C. MODE 1: V -> g_Vt f16 [bh][d][s].
// (unchanged from R14)
// ---------------------------------------------------------------------------
#define F4_AARR  8192
#define F4_BARR  4096
#define F4_STAGE (F4_AARR + F4_BARR)     // 12288
#define F4_NST   3
#define F4_SMEM  (F4_NST*F4_STAGE)       // 36864

template<int MODE>
__global__ __launch_bounds__(128, 4)
void gemm_f16_kernel(const __half* __restrict__ A, const __half* __restrict__ B,
                     float* __restrict__ C)
{
    extern __shared__ char smraw[];
    const uint32_t sbase = smem_u32(smraw);
    const int tid = threadIdx.x;
    const int wid = tid >> 5, lane = tid & 31;
    const int warp_m = wid >> 1, warp_n = wid & 1;
    const int m0 = blockIdx.y * 128, n0 = blockIdx.x * 64;

    float acc[4][4][4];
#pragma unroll
    for (int a = 0; a < 4; a++)
#pragma unroll
        for (int b = 0; b < 4; b++)
#pragma unroll
            for (int c = 0; c < 4; c++) acc[a][b][c] = 0.f;

    auto LOAD = [&](int it) {
        const uint32_t st = sbase + (it % F4_NST) * F4_STAGE;
        const char* gA = (const char*)A + (size_t)m0*2048 + it*64;
        const char* gB = (const char*)B + (size_t)n0*2048 + it*64;
#pragma unroll
        for (int i = 0; i < 4; i++) {
            int u = tid + i*128;
            int r = u >> 2, c4 = u & 3;
            cp_async16(st + SWZ64(r, c4), gA + (size_t)r*2048 + c4*16);
        }
#pragma unroll
        for (int i = 0; i < 2; i++) {
            int u = tid + i*128;
            int r = u >> 2, c4 = u & 3;
            cp_async16(st + F4_AARR + SWZ64(r, c4), gB + (size_t)r*2048 + c4*16);
        }
    };

    LOAD(0); CP_COMMIT();
    LOAD(1); CP_COMMIT();

    const int NIT = 32;
    for (int it = 0; it < NIT; it++) {
        CP_WAIT1();
        __syncthreads();
        if (it + 2 < NIT) LOAD(it + 2);
        CP_COMMIT();
        const uint32_t st = sbase + (it % F4_NST) * F4_STAGE;
#pragma unroll
        for (int j = 0; j < 2; j++) {
            const int c4 = j*2 + (lane >> 4);
            uint32_t a[4][4];
#pragma unroll
            for (int mf = 0; mf < 4; mf++) {
                const int r = warp_m*64 + mf*16 + (lane & 15);
                ldsm4(a[mf][0], a[mf][1], a[mf][2], a[mf][3], st + SWZ64(r, c4));
            }
#pragma unroll
            for (int nf2 = 0; nf2 < 2; nf2++) {
                const int rB = warp_n*32 + nf2*16 + (lane & 15);
                uint32_t r0, r1, r2, r3;
                ldsm4(r0, r1, r2, r3, st + F4_AARR + SWZ64(rB, c4));
                uint32_t b0[2] = {r0, r2}, b1[2] = {r1, r3};
#pragma unroll
                for (int mf = 0; mf < 4; mf++) {
                    mma_f16(acc[mf][2*nf2  ], a[mf], b0);
                    mma_f16(acc[mf][2*nf2+1], a[mf], b1);
                }
            }
        }
    }

    const int g = lane >> 2, t = lane & 3;
    if (MODE == 0) {
#pragma unroll
        for (int mf = 0; mf < 4; mf++) {
            const int row0 = m0 + warp_m*64 + mf*16 + g;
#pragma unroll
            for (int nf = 0; nf < 4; nf++) {
                const int col = n0 + warp_n*32 + nf*8 + t*2;
                *(float2*)&C[(size_t)row0*DD + col]     = make_float2(acc[mf][nf][0], acc[mf][nf][1]);
                *(float2*)&C[(size_t)(row0+8)*DD + col] = make_float2(acc[mf][nf][2], acc[mf][nf][3]);
            }
        }
    } else {
        __half* sm = (__half*)smraw;            // tile [tq 128][d 64], stride 72
        __syncthreads();
#pragma unroll
        for (int mf = 0; mf < 4; mf++) {
            const int rowl = warp_m*64 + mf*16 + g;
#pragma unroll
            for (int nf = 0; nf < 4; nf++) {
                const int col = warp_n*32 + nf*8 + t*2;
#pragma unroll
                for (int rr = 0; rr < 2; rr++) {
                    __half2 hv = __floats2half2_rn(acc[mf][nf][rr*2], acc[mf][nf][rr*2+1]);
                    *(__half2*)(sm + (size_t)(rowl + rr*8)*72 + col) = hv;
                }
            }
        }
        __syncthreads();
        const int dd = tid >> 1, th = tid & 1;
        const int h = (n0 + dd) >> 6, dl = (n0 + dd) & 63;
        const int b = m0 >> 11;
        const int tq0 = (m0 & 2047) + th*64;
        __half* dst = g_Vt + ((size_t)((b*HH + h)*DH + dl))*TT + tq0;
#pragma unroll
        for (int i8 = 0; i8 < 8; i8++) {
            __half tmp[8];
#pragma unroll
            for (int k = 0; k < 8; k++)
                tmp[k] = sm[(size_t)(th*64 + i8*8 + k)*72 + dd];
            *(uint4*)(dst + i8*8) = *(uint4*)tmp;
        }
    }
}

// ---------------------------------------------------------------------------
// Flash attention on HMMA — 64q / 128thr CTAs (1 warp/SMSP), 3 CTAs/SM,
// XOR-swizzled smem, 64-key chunks, 2-stage pipeline, lazy-max softmax.
// ---------------------------------------------------------------------------
#define AQ_BYTES  (64*256)               // 16384
#define AK_ARR    8192                   // 64 rows x 128B
#define A_NST     2
#define A_STAGE   (3*AK_ARR)             // Khi, Klo, V = 24576
#define A_SMEM    (AQ_BYTES + A_NST*A_STAGE)   // 65536

__global__ __launch_bounds__(128, 3)
void attn_mma_kernel()
{
    extern __shared__ char smraw[];
    const uint32_t sbase = smem_u32(smraw);
    const int tid = threadIdx.x, wid = tid >> 5, lane = tid & 31;
    const int bh = blockIdx.y;
    const int q0 = blockIdx.x * 64;

    const char* Qbase = (const char*)(g_Qs + ((size_t)bh*TT + q0) * 128);
    const char* Kbase = (const char*)(g_Ks + (size_t)bh*TT*128);
    const char* Vbase = (const char*)(g_Vt + (size_t)bh*DH*TT);

    // Q: 64 rows x 256B, swizzled (low 3 bits of 16B-col XOR row&7)
#pragma unroll
    for (int i = 0; i < 8; i++) {
        int u = tid + i*128;              // 0..1023
        int row = u >> 4, c16 = u & 15;
        uint32_t d = sbase + row*256 + ((((c16 & 7) ^ (row & 7)) | (c16 & 8)) << 4);
        cp_async16(d, Qbase + (size_t)row*256 + (c16 << 4));
    }

    auto LOADC = [&](int c) {
        const uint32_t s = sbase + AQ_BYTES + (c & 1) * A_STAGE;
        const char* ksrc = Kbase + (size_t)c*64*256;
        const char* vsrc = Vbase + (size_t)c*128;
#pragma unroll
        for (int i = 0; i < 4; i++) {
            int u = tid + i*128;          // 0..511
            int r = u >> 3, c8 = u & 7;
            uint32_t so = (uint32_t)(r*128 + (((c8 ^ r) & 7) << 4));
            cp_async16(s             + so, ksrc + (size_t)r*256 + (c8 << 4));        // Khi
            cp_async16(s +   AK_ARR + so, ksrc + (size_t)r*256 + 128 + (c8 << 4));   // Klo
            cp_async16(s + 2*AK_ARR + so, vsrc + (size_t)r*4096 + (c8 << 4));        // V [d][s]
        }
    };

    LOADC(0); CP_COMMIT();

    CP_WAIT0();               // Q + chunk 0 resident
    __syncthreads();

    // Q hi fragments resident; Q lo reloaded per chunk
    const int qrow = wid*16 + (lane & 15);
    const int qsw = qrow & 7;
    uint32_t qh[4][4];
#pragma unroll
    for (int j = 0; j < 4; j++) {
        int c16 = j*2 + (lane >> 4);
        uint32_t a = sbase + qrow*256 + (((c16 ^ qsw) & 7) << 4) + ((c16 & 8) << 4);
        ldsm4(qh[j][0], qh[j][1], qh[j][2], qh[j][3], a);
    }

    float of[8][4];
#pragma unroll
    for (int f = 0; f < 8; f++)
#pragma unroll
        for (int c4 = 0; c4 < 4; c4++) of[f][c4] = 0.f;
    float m0 = -1e30f, m1 = -1e30f, l0 = 0.f, l1 = 0.f;

    for (int c = 0; c < 32; c++) {
        if (c > 0) { CP_WAIT0(); __syncthreads(); }
        if (c + 1 < 32) LOADC(c + 1);
        CP_COMMIT();

        const uint32_t sK = sbase + AQ_BYTES + (c & 1) * A_STAGE;

        // ---- scores (64 keys -> 8 n-fragments) ----
        float sfr[8][4];
#pragma unroll
        for (int f = 0; f < 8; f++)
#pragma unroll
            for (int r4 = 0; r4 < 4; r4++) sfr[f][r4] = 0.f;

#pragma unroll
        for (int j = 0; j < 4; j++) {
            const int kc8 = j*2 + (lane >> 4);
            uint32_t ql[4];
            {
                int c16 = j*2 + (lane >> 4) + 8;
                uint32_t a = sbase + qrow*256 + (((c16 ^ qsw) & 7) << 4) + ((c16 & 8) << 4);
                ldsm4(ql[0], ql[1], ql[2], ql[3], a);
            }
#pragma unroll
            for (int nf2 = 0; nf2 < 4; nf2++) {       // K hi: qh + ql
                const int kr = nf2*16 + (lane & 15);
                uint32_t r0, r1, r2, r3;
                ldsm4(r0, r1, r2, r3, sK + kr*128 + (((kc8 ^ kr) & 7) << 4));
                uint32_t b0[2] = {r0, r2}, b1[2] = {r1, r3};
                mma_bf16(sfr[2*nf2  ], qh[j], b0);
                mma_bf16(sfr[2*nf2  ], ql,    b0);
                mma_bf16(sfr[2*nf2+1], qh[j], b1);
                mma_bf16(sfr[2*nf2+1], ql,    b1);
            }
#pragma unroll
            for (int nf2 = 0; nf2 < 4; nf2++) {       // K lo: qh only
                const int kr = nf2*16 + (lane & 15);
                uint32_t r0, r1, r2, r3;
                ldsm4(r0, r1, r2, r3, sK + AK_ARR + kr*128 + (((kc8 ^ kr) & 7) << 4));
                uint32_t b0[2] = {r0, r2}, b1[2] = {r1, r3};
                mma_bf16(sfr[2*nf2  ], qh[j], b0);
                mma_bf16(sfr[2*nf2+1], qh[j], b1);
            }
        }

        // ---- lazy online softmax (exp2 domain) ----
        float mxl0 = sfr[0][0], mxl1 = sfr[0][2];
#pragma unroll
        for (int f = 0; f < 8; f++) {
            mxl0 = fmaxf(mxl0, fmaxf(sfr[f][0], sfr[f][1]));
            mxl1 = fmaxf(mxl1, fmaxf(sfr[f][2], sfr[f][3]));
        }
        if (__ballot_sync(0xffffffffu, (mxl0 > m0) || (mxl1 > m1))) {
            float mx0 = mxl0, mx1 = mxl1;
            mx0 = fmaxf(mx0, __shfl_xor_sync(0xffffffffu, mx0, 1));
            mx0 = fmaxf(mx0, __shfl_xor_sync(0xffffffffu, mx0, 2));
            mx1 = fmaxf(mx1, __shfl_xor_sync(0xffffffffu, mx1, 1));
            mx1 = fmaxf(mx1, __shfl_xor_sync(0xffffffffu, mx1, 2));
            const float m0n = fmaxf(m0, mx0 + 1.0f);
            const float m1n = fmaxf(m1, mx1 + 1.0f);
            const float corr0 = ex2f(m0 - m0n), corr1 = ex2f(m1 - m1n);
            l0 *= corr0; l1 *= corr1;
#pragma unroll
            for (int f = 0; f < 8; f++) {
                of[f][0] *= corr0; of[f][1] *= corr0;
                of[f][2] *= corr1; of[f][3] *= corr1;
            }
            m0 = m0n; m1 = m1n;
        }

        uint32_t pa[4][4];
        float l0a = 0.f, l1a = 0.f;
#pragma unroll
        for (int f = 0; f < 8; f++) {
            uint32_t p01 = ex2_h2(f2h2u(sfr[f][0] - m0, sfr[f][1] - m0));
            uint32_t p23 = ex2_h2(f2h2u(sfr[f][2] - m1, sfr[f][3] - m1));
            const int j = f >> 1;
            if (f & 1) { pa[j][2] = p01; pa[j][3] = p23; }
            else       { pa[j][0] = p01; pa[j][1] = p23; }
            float2 a = h2u2f2(p01); l0a += a.x + a.y;
            float2 bs = h2u2f2(p23); l1a += bs.x + bs.y;
        }
        l0 += l0a;
        l1 += l1a;

        // ---- PV: single f16 V ----
#pragma unroll
        for (int j = 0; j < 4; j++) {
            const int kc8 = j*2 + (lane >> 4);
#pragma unroll
            for (int nf2 = 0; nf2 < 4; nf2++) {
                const int kr = nf2*16 + (lane & 15);
                uint32_t r0, r1, r2, r3;
                ldsm4(r0, r1, r2, r3, sK + 2*AK_ARR + kr*128 + (((kc8 ^ kr) & 7) << 4));
                uint32_t b0[2] = {r0, r2}, b1[2] = {r1, r3};
                mma_f16(of[2*nf2  ], pa[j], b0);
                mma_f16(of[2*nf2+1], pa[j], b1);
            }
        }
    }

    // epilogue: lane-reduce l, normalize, write f16 O
    l0 += __shfl_xor_sync(0xffffffffu, l0, 1);
    l0 += __shfl_xor_sync(0xffffffffu, l0, 2);
    l1 += __shfl_xor_sync(0xffffffffu, l1, 1);
    l1 += __shfl_xor_sync(0xffffffffu, l1, 2);
    const float inv0 = 1.f / l0, inv1 = 1.f / l1;
    const int b = bh >> 4, h = bh & 15;
    const int g = lane >> 2, t = lane & 3;
    const int qr = q0 + wid*16 + g;
#pragma unroll
    for (int f = 0; f < 8; f++) {
        const int col = h*DH + f*8 + t*2;
#pragma unroll
        for (int rr = 0; rr < 2; rr++) {
            const size_t row = (size_t)(b*TT) + qr + rr*8;
            const float inv = rr ? inv1 : inv0;
            __half2 hv = __floats2half2_rn(of[f][rr*2] * inv, of[f][rr*2+1] * inv);
            *(__half2*)&g_Oh[row*DD + col] = hv;
        }
    }
}

// ---------------------------------------------------------------------------
// Launch. Inputs: 0=x, 1=mask, 2=Wq, 3=Wk, 4=Wv, 5=Wo, 6=S_q, 7=S_k
// Order: prep(1), Vgemm(2), QKgemm(3), attn(4 = ncu slot), outgemm(5).
// ---------------------------------------------------------------------------
extern "C" void kernel_launch(void* const* d_in, const int* in_sizes, int n_in,
                              void* d_out, int out_size)
{
    const float* x  = (const float*)d_in[0];
    const float* Wq = (const float*)d_in[2];
    const float* Wk = (const float*)d_in[3];
    const float* Wv = (const float*)d_in[4];
    const float* Wo = (const float*)d_in[5];
    const float* Sq = (const float*)d_in[6];
    const float* Sk = (const float*)d_in[7];
    float* outp = (float*)d_out;

    __nv_bfloat16 *dA2, *dWQ2, *dWK2;
    __half *dAh, *dOh, *dWVh, *dWOh;
    cudaGetSymbolAddress((void**)&dA2,  g_A2);
    cudaGetSymbolAddress((void**)&dAh,  g_Ah);
    cudaGetSymbolAddress((void**)&dOh,  g_Oh);
    cudaGetSymbolAddress((void**)&dWQ2, g_WQ2);
    cudaGetSymbolAddress((void**)&dWK2, g_WK2);
    cudaGetSymbolAddress((void**)&dWVh, g_WVh);
    cudaGetSymbolAddress((void**)&dWOh, g_WOh);

    cudaFuncSetAttribute(gemm_qk_kernel,     cudaFuncAttributeMaxDynamicSharedMemorySize, Q4_SMEM);
    cudaFuncSetAttribute(gemm_f16_kernel<0>, cudaFuncAttributeMaxDynamicSharedMemorySize, F4_SMEM);
    cudaFuncSetAttribute(gemm_f16_kernel<1>, cudaFuncAttributeMaxDynamicSharedMemorySize, F4_SMEM);
    cudaFuncSetAttribute(attn_mma_kernel,    cudaFuncAttributeMaxDynamicSharedMemorySize, A_SMEM);

    // 1) prep: x split/f16 + weight fold/split (one launch)
    prep_kernel<<<CVT_BLKS + 256, 256>>>(x, Wq, Wk, Wv, Wo, Sq, Sk);

    // 2) V projection (1-term f16, 4 CTAs/SM) -> g_Vt transposed
    gemm_f16_kernel<1><<<dim3(16, MM/128), 128, F4_SMEM>>>(dAh, dWVh, nullptr);

    // 3) Q/K projections (3-term bf16, 4 CTAs/SM)
    const float qscale = 0.125f * 1.4426950408889634f;   // scale * log2(e)
    gemm_qk_kernel<<<dim3(32, MM/128), 128, Q4_SMEM>>>(dA2, dWQ2, dWK2, qscale);

    // 4) flash attention (64q CTAs, 3/SM) -> g_Oh f16   [ncu capture slot]
    attn_mma_kernel<<<dim3(TT/64, BH), 128, A_SMEM>>>();

    // 5) output projection (1-term f16, 4 CTAs/SM) -> d_out fp32
    gemm_f16_kernel<0><<<dim3(16, MM/128), 128, F4_SMEM>>>(dOh, dWOh, outp);
}

// round 17
// speedup vs baseline: 1.0572x; 1.0572x over previous
#include <cuda_runtime.h>
#include <cuda_bf16.h>
#include <cuda_fp16.h>
#include <math.h>
#include <stdint.h>

// Shapes (fixed)
#define BB 2
#define TT 2048
#define DD 1024
#define HH 16
#define DH 64
#define MM (BB*TT)   // 4096
#define BH (BB*HH)   // 32

// ---------------------------------------------------------------------------
// Scratch (no cudaMalloc allowed)
// ---------------------------------------------------------------------------
__device__ __nv_bfloat16 g_A2 [MM*2*DD];      // x split [rows][hi1024|lo1024]
__device__ __half        g_Ah [MM*DD];        // x plain f16 (for V gemm)
__device__ __half        g_Oh [MM*DD];        // attention output f16
__device__ __nv_bfloat16 g_WQ2[DD*2*DD];      // folded Wq split
__device__ __nv_bfloat16 g_WK2[DD*2*DD];      // folded Wk split
__device__ __half        g_WVh[DD*DD];        // Wv f16
__device__ __half        g_WOh[DD*DD];        // Wo f16
__device__ __nv_bfloat16 g_Qs[BH*TT*128];     // [bh][t][hi64|lo64], Q pre-scaled
__device__ __nv_bfloat16 g_Ks[BH*TT*128];     // [bh][t][hi64|lo64]
__device__ __half        g_Vt[BH*DH*TT];      // [bh][d][s]  (f16, transposed)

// ---------------------------------------------------------------------------
// PTX helpers (sm_80-level only — ptxas targets plain sm_103, no tcgen05/TMA)
// ---------------------------------------------------------------------------
__device__ __forceinline__ uint32_t smem_u32(const void* p) {
    uint32_t a;
    asm("{ .reg .u64 t; cvta.to.shared.u64 t, %1; cvt.u32.u64 %0, t; }" : "=r"(a) : "l"(p));
    return a;
}
__device__ __forceinline__ void cp_async16(uint32_t dst, const void* src) {
    asm volatile("cp.async.cg.shared.global [%0], [%1], 16;\n" :: "r"(dst), "l"(src));
}
#define CP_COMMIT() asm volatile("cp.async.commit_group;\n" ::: "memory")
#define CP_WAIT0()  asm volatile("cp.async.wait_group 0;\n" ::: "memory")
#define CP_WAIT1()  asm volatile("cp.async.wait_group 1;\n" ::: "memory")

__device__ __forceinline__ void ldsm4(uint32_t &r0, uint32_t &r1, uint32_t &r2, uint32_t &r3,
                                      uint32_t addr) {
    asm volatile("ldmatrix.sync.aligned.m8n8.x4.shared.b16 {%0,%1,%2,%3}, [%4];"
                 : "=r"(r0), "=r"(r1), "=r"(r2), "=r"(r3) : "r"(addr));
}
__device__ __forceinline__ void mma_bf16(float* c, const uint32_t* a, const uint32_t* b) {
    asm volatile("mma.sync.aligned.m16n8k16.row.col.f32.bf16.bf16.f32 "
                 "{%0,%1,%2,%3}, {%4,%5,%6,%7}, {%8,%9}, {%0,%1,%2,%3};"
                 : "+f"(c[0]), "+f"(c[1]), "+f"(c[2]), "+f"(c[3])
                 : "r"(a[0]), "r"(a[1]), "r"(a[2]), "r"(a[3]), "r"(b[0]), "r"(b[1]));
}
__device__ __forceinline__ void mma_f16(float* c, const uint32_t* a, const uint32_t* b) {
    asm volatile("mma.sync.aligned.m16n8k16.row.col.f32.f16.f16.f32 "
                 "{%0,%1,%2,%3}, {%4,%5,%6,%7}, {%8,%9}, {%0,%1,%2,%3};"
                 : "+f"(c[0]), "+f"(c[1]), "+f"(c[2]), "+f"(c[3])
                 : "r"(a[0]), "r"(a[1]), "r"(a[2]), "r"(a[3]), "r"(b[0]), "r"(b[1]));
}
__device__ __forceinline__ float ex2f(float x) {
    float r; asm("ex2.approx.ftz.f32 %0, %1;" : "=f"(r) : "f"(x)); return r;
}
__device__ __forceinline__ uint32_t ex2_h2(uint32_t x) {
    uint32_t r; asm("ex2.approx.f16x2 %0, %1;" : "=r"(r) : "r"(x)); return r;
}
__device__ __forceinline__ uint32_t f2h2u(float a, float b) {
    __half2 h = __floats2half2_rn(a, b);
    return *reinterpret_cast<uint32_t*>(&h);
}
__device__ __forceinline__ float2 h2u2f2(uint32_t u) {
    __half2 h = *reinterpret_cast<__half2*>(&u);
    return __half22float2(h);
}
__device__ __forceinline__ uint32_t pack_bf16(float a, float b) {
    __nv_bfloat162 h = __floats2bfloat162_rn(a, b);
    return *reinterpret_cast<uint32_t*>(&h);
}
__device__ __forceinline__ void split2(float v0, float v1, uint32_t &hi, uint32_t &lo) {
    __nv_bfloat16 h0 = __float2bfloat16(v0);
    __nv_bfloat16 h1 = __float2bfloat16(v1);
    float l0 = v0 - __bfloat162float(h0);
    float l1 = v1 - __bfloat162float(h1);
    uint32_t u0 = (uint32_t)*reinterpret_cast<uint16_t*>(&h0);
    uint32_t u1 = (uint32_t)*reinterpret_cast<uint16_t*>(&h1);
    hi = u0 | (u1 << 16);
    lo = pack_bf16(l0, l1);
}

// 64B-row swizzle: 16B-chunk c4 XOR bits (r>>1)&3 -> conflict-free ldsm
#define SWZ64(r, c4) ((uint32_t)((r)*64 + ((((c4) ^ (((r) >> 1) & 3)) & 3) << 4)))

// ---------------------------------------------------------------------------
// weff_all: z=0/1 fold+split Wq/Wk with S; z=2/3 plain f16 of Wv/Wo.
// (separate kernel — keeps reg-heavy fold out of the cvt launch)
// ---------------------------------------------------------------------------
__global__ __launch_bounds__(256)
void weff_all_kernel(const float* __restrict__ Wq, const float* __restrict__ Wk,
                     const float* __restrict__ Wv, const float* __restrict__ Wo,
                     const float* __restrict__ Sq, const float* __restrict__ Sk)
{
    const int h = blockIdx.y;
    const int z = blockIdx.z;
    const int d = blockIdx.x * 256 + threadIdx.x;

    if (z < 2) {
        const float* __restrict__ W = z ? Wk : Wq;
        const float* __restrict__ S = z ? Sk : Sq;
        __nv_bfloat16* __restrict__ outp = z ? g_WK2 : g_WQ2;

        __shared__ float s_s[DH*DH];
        for (int i = threadIdx.x; i < DH*DH; i += 256) s_s[i] = S[h*DH*DH + i];
        __syncthreads();

        float acc[DH];
#pragma unroll
        for (int e = 0; e < DH; e++) acc[e] = 0.f;
        for (int c = 0; c < DH; c++) {
            const float w = W[(h*DH + c)*DD + d];
#pragma unroll
            for (int e = 0; e < DH; e++) acc[e] += w * s_s[c*DH + e];
        }
#pragma unroll
        for (int e = 0; e < DH; e++) {
            float v = acc[e];
            __nv_bfloat16 hi = __float2bfloat16(v);
            float lo = v - __bfloat162float(hi);
            outp[(size_t)(h*DH + e)*2048 + d] = hi;
            outp[(size_t)(h*DH + e)*2048 + 1024 + d] = __float2bfloat16(lo);
        }
    } else {
        const float* __restrict__ W = (z == 2) ? Wv : Wo;
        __half* __restrict__ outp = (z == 2) ? g_WVh : g_WOh;
        for (int c = 0; c < DH; c++) {
            const int row = h*DH + c;
            outp[(size_t)row*DD + d] = __float2half_rn(W[(size_t)row*DD + d]);
        }
    }
}

// ---------------------------------------------------------------------------
// x -> bf16 hi/lo split + f16 copy (separate, low-reg, high-occupancy)
// ---------------------------------------------------------------------------
__global__ __launch_bounds__(256)
void cvt_split_kernel(const float* __restrict__ src)
{
    int i = blockIdx.x * 256 + threadIdx.x;
    int r = i >> 10, c = i & 1023;
    float v = src[i];
    __nv_bfloat16 hi = __float2bfloat16(v);
    float lof = v - __bfloat162float(hi);
    g_A2[(size_t)r*2048 + c] = hi;
    g_A2[(size_t)r*2048 + 1024 + c] = __float2bfloat16(lof);
    g_Ah[i] = __float2half_rn(v);
}

// ---------------------------------------------------------------------------
// QK GEMM (3-term bf16), 128-thread CTA (4 warps, 1/SMSP), 4 CTAs/SM.
// Tile 128x64, BK=32, 2 stages. grid (32, 32): x>>4 = 0 -> Q, 1 -> K.
// ---------------------------------------------------------------------------
#define Q4_AARR  8192
#define Q4_BARR  4096
#define Q4_STAGE (2*Q4_AARR + 2*Q4_BARR) // 24576
#define Q4_NST   2
#define Q4_SMEM  (Q4_NST*Q4_STAGE)       // 49152

__global__ __launch_bounds__(128, 4)
void gemm_qk_kernel(const __nv_bfloat16* __restrict__ A2,
                    const __nv_bfloat16* __restrict__ Bq,
                    const __nv_bfloat16* __restrict__ Bk, float qscale)
{
    extern __shared__ char smraw[];
    const uint32_t sbase = smem_u32(smraw);
    const int tid = threadIdx.x;
    const int wid = tid >> 5, lane = tid & 31;
    const int warp_m = wid >> 1, warp_n = wid & 1;
    const int m0 = blockIdx.y * 128;
    const int nb = blockIdx.x >> 4;                     // 0=Q, 1=K
    const int n0 = (blockIdx.x & 15) * 64;
    const __nv_bfloat16* __restrict__ B2 = nb ? Bk : Bq;

    float acc[4][4][4];
#pragma unroll
    for (int a = 0; a < 4; a++)
#pragma unroll
        for (int b = 0; b < 4; b++)
#pragma unroll
            for (int c = 0; c < 4; c++) acc[a][b][c] = 0.f;

    auto LOAD = [&](int it) {
        const uint32_t st = sbase + (it & 1) * Q4_STAGE;
        const char* gA = (const char*)A2 + (size_t)m0*4096 + it*64;
        const char* gB = (const char*)B2 + (size_t)n0*4096 + it*64;
#pragma unroll
        for (int i = 0; i < 4; i++) {
            int u = tid + i*128;
            int r = u >> 2, c4 = u & 3;
            const uint32_t so = SWZ64(r, c4);
            const size_t go = (size_t)r*4096 + c4*16;
            cp_async16(st           + so, gA + go);
            cp_async16(st + Q4_AARR + so, gA + 2048 + go);
        }
#pragma unroll
        for (int i = 0; i < 2; i++) {
            int u = tid + i*128;
            int r = u >> 2, c4 = u & 3;
            const uint32_t so = SWZ64(r, c4);
            const size_t go = (size_t)r*4096 + c4*16;
            cp_async16(st + 2*Q4_AARR           + so, gB + go);
            cp_async16(st + 2*Q4_AARR + Q4_BARR + so, gB + 2048 + go);
        }
    };

    LOAD(0); CP_COMMIT();

    const int NIT = 32;
    for (int it = 0; it < NIT; it++) {
        CP_WAIT0();
        __syncthreads();
        if (it + 1 < NIT) LOAD(it + 1);
        CP_COMMIT();
        const uint32_t st = sbase + (it & 1) * Q4_STAGE;
#pragma unroll
        for (int j = 0; j < 2; j++) {
            const int c4 = j*2 + (lane >> 4);
            uint32_t ah[4][4], al[4][4];
#pragma unroll
            for (int mf = 0; mf < 4; mf++) {
                const int r = warp_m*64 + mf*16 + (lane & 15);
                ldsm4(ah[mf][0], ah[mf][1], ah[mf][2], ah[mf][3], st + SWZ64(r, c4));
                ldsm4(al[mf][0], al[mf][1], al[mf][2], al[mf][3], st + Q4_AARR + SWZ64(r, c4));
            }
#pragma unroll
            for (int nf2 = 0; nf2 < 2; nf2++) {
                const int rB = warp_n*32 + nf2*16 + (lane & 15);
                uint32_t r0, r1, r2, r3;
                ldsm4(r0, r1, r2, r3, st + 2*Q4_AARR + SWZ64(rB, c4));     // B hi
                {
                    uint32_t b0[2] = {r0, r2}, b1[2] = {r1, r3};
#pragma unroll
                    for (int mf = 0; mf < 4; mf++) {
                        mma_bf16(acc[mf][2*nf2  ], ah[mf], b0);
                        mma_bf16(acc[mf][2*nf2  ], al[mf], b0);
                        mma_bf16(acc[mf][2*nf2+1], ah[mf], b1);
                        mma_bf16(acc[mf][2*nf2+1], al[mf], b1);
                    }
                }
                ldsm4(r0, r1, r2, r3, st + 2*Q4_AARR + Q4_BARR + SWZ64(rB, c4));  // B lo
                {
                    uint32_t b0[2] = {r0, r2}, b1[2] = {r1, r3};
#pragma unroll
                    for (int mf = 0; mf < 4; mf++) {
                        mma_bf16(acc[mf][2*nf2  ], ah[mf], b0);
                        mma_bf16(acc[mf][2*nf2+1], ah[mf], b1);
                    }
                }
            }
        }
    }

    const int g = lane >> 2, t = lane & 3;
    __nv_bfloat16* dst = (nb == 0) ? g_Qs : g_Ks;
    const float sc = (nb == 0) ? qscale : 1.0f;
#pragma unroll
    for (int mf = 0; mf < 4; mf++) {
        const int row0 = m0 + warp_m*64 + mf*16 + g;
#pragma unroll
        for (int nf = 0; nf < 4; nf++) {
            const int col = n0 + warp_n*32 + nf*8 + t*2;
            const int h = col >> 6, e = col & 63;
#pragma unroll
            for (int rr = 0; rr < 2; rr++) {
                const int row = row0 + rr*8;
                const int b = row >> 11, tq = row & 2047;
                const size_t base = ((size_t)(b*HH + h)*TT + tq) << 7;
                uint32_t hi, lo;
                split2(acc[mf][nf][rr*2] * sc, acc[mf][nf][rr*2+1] * sc, hi, lo);
                *(uint32_t*)&dst[base + e]      = hi;
                *(uint32_t*)&dst[base + 64 + e] = lo;
            }
        }
    }
}

// ---------------------------------------------------------------------------
// 1-term f16 GEMM, 128-thread CTA (4 warps), 4 CTAs/SM. Tile 128x64, BK=32,
// 3 stages. grid (16, 32). MODE 0: fp32 C. MODE 1: V -> g_Vt f16 [bh][d][s].
// ---------------------------------------------------------------------------
#define F4_AARR  8192
#define F4_BARR  4096
#define F4_STAGE (F4_AARR + F4_BARR)     // 12288
#define F4_NST   3
#define F4_SMEM  (F4_NST*F4_STAGE)       // 36864

template<int MODE>
__global__ __launch_bounds__(128, 4)
void gemm_f16_kernel(const __half* __restrict__ A, const __half* __restrict__ B,
                     float* __restrict__ C)
{
    extern __shared__ char smraw[];
    const uint32_t sbase = smem_u32(smraw);
    const int tid = threadIdx.x;
    const int wid = tid >> 5, lane = tid & 31;
    const int warp_m = wid >> 1, warp_n = wid & 1;
    const int m0 = blockIdx.y * 128, n0 = blockIdx.x * 64;

    float acc[4][4][4];
#pragma unroll
    for (int a = 0; a < 4; a++)
#pragma unroll
        for (int b = 0; b < 4; b++)
#pragma unroll
            for (int c = 0; c < 4; c++) acc[a][b][c] = 0.f;

    auto LOAD = [&](int it) {
        const uint32_t st = sbase + (it % F4_NST) * F4_STAGE;
        const char* gA = (const char*)A + (size_t)m0*2048 + it*64;
        const char* gB = (const char*)B + (size_t)n0*2048 + it*64;
#pragma unroll
        for (int i = 0; i < 4; i++) {
            int u = tid + i*128;
            int r = u >> 2, c4 = u & 3;
            cp_async16(st + SWZ64(r, c4), gA + (size_t)r*2048 + c4*16);
        }
#pragma unroll
        for (int i = 0; i < 2; i++) {
            int u = tid + i*128;
            int r = u >> 2, c4 = u & 3;
            cp_async16(st + F4_AARR + SWZ64(r, c4), gB + (size_t)r*2048 + c4*16);
        }
    };

    LOAD(0); CP_COMMIT();
    LOAD(1); CP_COMMIT();

    const int NIT = 32;
    for (int it = 0; it < NIT; it++) {
        CP_WAIT1();
        __syncthreads();
        if (it + 2 < NIT) LOAD(it + 2);
        CP_COMMIT();
        const uint32_t st = sbase + (it % F4_NST) * F4_STAGE;
#pragma unroll
        for (int j = 0; j < 2; j++) {
            const int c4 = j*2 + (lane >> 4);
            uint32_t a[4][4];
#pragma unroll
            for (int mf = 0; mf < 4; mf++) {
                const int r = warp_m*64 + mf*16 + (lane & 15);
                ldsm4(a[mf][0], a[mf][1], a[mf][2], a[mf][3], st + SWZ64(r, c4));
            }
#pragma unroll
            for (int nf2 = 0; nf2 < 2; nf2++) {
                const int rB = warp_n*32 + nf2*16 + (lane & 15);
                uint32_t r0, r1, r2, r3;
                ldsm4(r0, r1, r2, r3, st + F4_AARR + SWZ64(rB, c4));
                uint32_t b0[2] = {r0, r2}, b1[2] = {r1, r3};
#pragma unroll
                for (int mf = 0; mf < 4; mf++) {
                    mma_f16(acc[mf][2*nf2  ], a[mf], b0);
                    mma_f16(acc[mf][2*nf2+1], a[mf], b1);
                }
            }
        }
    }

    const int g = lane >> 2, t = lane & 3;
    if (MODE == 0) {
#pragma unroll
        for (int mf = 0; mf < 4; mf++) {
            const int row0 = m0 + warp_m*64 + mf*16 + g;
#pragma unroll
            for (int nf = 0; nf < 4; nf++) {
                const int col = n0 + warp_n*32 + nf*8 + t*2;
                *(float2*)&C[(size_t)row0*DD + col]     = make_float2(acc[mf][nf][0], acc[mf][nf][1]);
                *(float2*)&C[(size_t)(row0+8)*DD + col] = make_float2(acc[mf][nf][2], acc[mf][nf][3]);
            }
        }
    } else {
        __half* sm = (__half*)smraw;            // tile [tq 128][d 64], stride 72
        __syncthreads();
#pragma unroll
        for (int mf = 0; mf < 4; mf++) {
            const int rowl = warp_m*64 + mf*16 + g;
#pragma unroll
            for (int nf = 0; nf < 4; nf++) {
                const int col = warp_n*32 + nf*8 + t*2;
#pragma unroll
                for (int rr = 0; rr < 2; rr++) {
                    __half2 hv = __floats2half2_rn(acc[mf][nf][rr*2], acc[mf][nf][rr*2+1]);
                    *(__half2*)(sm + (size_t)(rowl + rr*8)*72 + col) = hv;
                }
            }
        }
        __syncthreads();
        const int dd = tid >> 1, th = tid & 1;
        const int h = (n0 + dd) >> 6, dl = (n0 + dd) & 63;
        const int b = m0 >> 11;
        const int tq0 = (m0 & 2047) + th*64;
        __half* dst = g_Vt + ((size_t)((b*HH + h)*DH + dl))*TT + tq0;
#pragma unroll
        for (int i8 = 0; i8 < 8; i8++) {
            __half tmp[8];
#pragma unroll
            for (int k = 0; k < 8; k++)
                tmp[k] = sm[(size_t)(th*64 + i8*8 + k)*72 + dd];
            *(uint4*)(dst + i8*8) = *(uint4*)tmp;
        }
    }
}

// ---------------------------------------------------------------------------
// Flash attention on HMMA — 64q / 128thr CTAs (1 warp/SMSP), 3 CTAs/SM,
// XOR-swizzled smem, 64-key chunks, 2-stage pipeline, lazy-max softmax.
// (= R15 attention, kept)
// ---------------------------------------------------------------------------
#define AQ_BYTES  (64*256)               // 16384
#define AK_ARR    8192                   // 64 rows x 128B
#define A_NST     2
#define A_STAGE   (3*AK_ARR)             // Khi, Klo, V = 24576
#define A_SMEM    (AQ_BYTES + A_NST*A_STAGE)   // 65536

__global__ __launch_bounds__(128, 3)
void attn_mma_kernel()
{
    extern __shared__ char smraw[];
    const uint32_t sbase = smem_u32(smraw);
    const int tid = threadIdx.x, wid = tid >> 5, lane = tid & 31;
    const int bh = blockIdx.y;
    const int q0 = blockIdx.x * 64;

    const char* Qbase = (const char*)(g_Qs + ((size_t)bh*TT + q0) * 128);
    const char* Kbase = (const char*)(g_Ks + (size_t)bh*TT*128);
    const char* Vbase = (const char*)(g_Vt + (size_t)bh*DH*TT);

    // Q: 64 rows x 256B, swizzled
#pragma unroll
    for (int i = 0; i < 8; i++) {
        int u = tid + i*128;
        int row = u >> 4, c16 = u & 15;
        uint32_t d = sbase + row*256 + ((((c16 & 7) ^ (row & 7)) | (c16 & 8)) << 4);
        cp_async16(d, Qbase + (size_t)row*256 + (c16 << 4));
    }

    auto LOADC = [&](int c) {
        const uint32_t s = sbase + AQ_BYTES + (c & 1) * A_STAGE;
        const char* ksrc = Kbase + (size_t)c*64*256;
        const char* vsrc = Vbase + (size_t)c*128;
#pragma unroll
        for (int i = 0; i < 4; i++) {
            int u = tid + i*128;
            int r = u >> 3, c8 = u & 7;
            uint32_t so = (uint32_t)(r*128 + (((c8 ^ r) & 7) << 4));
            cp_async16(s             + so, ksrc + (size_t)r*256 + (c8 << 4));
            cp_async16(s +   AK_ARR + so, ksrc + (size_t)r*256 + 128 + (c8 << 4));
            cp_async16(s + 2*AK_ARR + so, vsrc + (size_t)r*4096 + (c8 << 4));
        }
    };

    LOADC(0); CP_COMMIT();

    CP_WAIT0();
    __syncthreads();

    const int qrow = wid*16 + (lane & 15);
    const int qsw = qrow & 7;
    uint32_t qh[4][4];
#pragma unroll
    for (int j = 0; j < 4; j++) {
        int c16 = j*2 + (lane >> 4);
        uint32_t a = sbase + qrow*256 + (((c16 ^ qsw) & 7) << 4) + ((c16 & 8) << 4);
        ldsm4(qh[j][0], qh[j][1], qh[j][2], qh[j][3], a);
    }

    float of[8][4];
#pragma unroll
    for (int f = 0; f < 8; f++)
#pragma unroll
        for (int c4 = 0; c4 < 4; c4++) of[f][c4] = 0.f;
    float m0 = -1e30f, m1 = -1e30f, l0 = 0.f, l1 = 0.f;

    for (int c = 0; c < 32; c++) {
        if (c > 0) { CP_WAIT0(); __syncthreads(); }
        if (c + 1 < 32) LOADC(c + 1);
        CP_COMMIT();

        const uint32_t sK = sbase + AQ_BYTES + (c & 1) * A_STAGE;

        float sfr[8][4];
#pragma unroll
        for (int f = 0; f < 8; f++)
#pragma unroll
            for (int r4 = 0; r4 < 4; r4++) sfr[f][r4] = 0.f;

#pragma unroll
        for (int j = 0; j < 4; j++) {
            const int kc8 = j*2 + (lane >> 4);
            uint32_t ql[4];
            {
                int c16 = j*2 + (lane >> 4) + 8;
                uint32_t a = sbase + qrow*256 + (((c16 ^ qsw) & 7) << 4) + ((c16 & 8) << 4);
                ldsm4(ql[0], ql[1], ql[2], ql[3], a);
            }
#pragma unroll
            for (int nf2 = 0; nf2 < 4; nf2++) {       // K hi: qh + ql
                const int kr = nf2*16 + (lane & 15);
                uint32_t r0, r1, r2, r3;
                ldsm4(r0, r1, r2, r3, sK + kr*128 + (((kc8 ^ kr) & 7) << 4));
                uint32_t b0[2] = {r0, r2}, b1[2] = {r1, r3};
                mma_bf16(sfr[2*nf2  ], qh[j], b0);
                mma_bf16(sfr[2*nf2  ], ql,    b0);
                mma_bf16(sfr[2*nf2+1], qh[j], b1);
                mma_bf16(sfr[2*nf2+1], ql,    b1);
            }
#pragma unroll
            for (int nf2 = 0; nf2 < 4; nf2++) {       // K lo: qh only
                const int kr = nf2*16 + (lane & 15);
                uint32_t r0, r1, r2, r3;
                ldsm4(r0, r1, r2, r3, sK + AK_ARR + kr*128 + (((kc8 ^ kr) & 7) << 4));
                uint32_t b0[2] = {r0, r2}, b1[2] = {r1, r3};
                mma_bf16(sfr[2*nf2  ], qh[j], b0);
                mma_bf16(sfr[2*nf2+1], qh[j], b1);
            }
        }

        float mxl0 = sfr[0][0], mxl1 = sfr[0][2];
#pragma unroll
        for (int f = 0; f < 8; f++) {
            mxl0 = fmaxf(mxl0, fmaxf(sfr[f][0], sfr[f][1]));
            mxl1 = fmaxf(mxl1, fmaxf(sfr[f][2], sfr[f][3]));
        }
        if (__ballot_sync(0xffffffffu, (mxl0 > m0) || (mxl1 > m1))) {
            float mx0 = mxl0, mx1 = mxl1;
            mx0 = fmaxf(mx0, __shfl_xor_sync(0xffffffffu, mx0, 1));
            mx0 = fmaxf(mx0, __shfl_xor_sync(0xffffffffu, mx0, 2));
            mx1 = fmaxf(mx1, __shfl_xor_sync(0xffffffffu, mx1, 1));
            mx1 = fmaxf(mx1, __shfl_xor_sync(0xffffffffu, mx1, 2));
            const float m0n = fmaxf(m0, mx0 + 1.0f);
            const float m1n = fmaxf(m1, mx1 + 1.0f);
            const float corr0 = ex2f(m0 - m0n), corr1 = ex2f(m1 - m1n);
            l0 *= corr0; l1 *= corr1;
#pragma unroll
            for (int f = 0; f < 8; f++) {
                of[f][0] *= corr0; of[f][1] *= corr0;
                of[f][2] *= corr1; of[f][3] *= corr1;
            }
            m0 = m0n; m1 = m1n;
        }

        uint32_t pa[4][4];
        float l0a = 0.f, l1a = 0.f;
#pragma unroll
        for (int f = 0; f < 8; f++) {
            uint32_t p01 = ex2_h2(f2h2u(sfr[f][0] - m0, sfr[f][1] - m0));
            uint32_t p23 = ex2_h2(f2h2u(sfr[f][2] - m1, sfr[f][3] - m1));
            const int j = f >> 1;
            if (f & 1) { pa[j][2] = p01; pa[j][3] = p23; }
            else       { pa[j][0] = p01; pa[j][1] = p23; }
            float2 a = h2u2f2(p01); l0a += a.x + a.y;
            float2 bs = h2u2f2(p23); l1a += bs.x + bs.y;
        }
        l0 += l0a;
        l1 += l1a;

#pragma unroll
        for (int j = 0; j < 4; j++) {
            const int kc8 = j*2 + (lane >> 4);
#pragma unroll
            for (int nf2 = 0; nf2 < 4; nf2++) {
                const int kr = nf2*16 + (lane & 15);
                uint32_t r0, r1, r2, r3;
                ldsm4(r0, r1, r2, r3, sK + 2*AK_ARR + kr*128 + (((kc8 ^ kr) & 7) << 4));
                uint32_t b0[2] = {r0, r2}, b1[2] = {r1, r3};
                mma_f16(of[2*nf2  ], pa[j], b0);
                mma_f16(of[2*nf2+1], pa[j], b1);
            }
        }
    }

    l0 += __shfl_xor_sync(0xffffffffu, l0, 1);
    l0 += __shfl_xor_sync(0xffffffffu, l0, 2);
    l1 += __shfl_xor_sync(0xffffffffu, l1, 1);
    l1 += __shfl_xor_sync(0xffffffffu, l1, 2);
    const float inv0 = 1.f / l0, inv1 = 1.f / l1;
    const int b = bh >> 4, h = bh & 15;
    const int g = lane >> 2, t = lane & 3;
    const int qr = q0 + wid*16 + g;
#pragma unroll
    for (int f = 0; f < 8; f++) {
        const int col = h*DH + f*8 + t*2;
#pragma unroll
        for (int rr = 0; rr < 2; rr++) {
            const size_t row = (size_t)(b*TT) + qr + rr*8;
            const float inv = rr ? inv1 : inv0;
            __half2 hv = __floats2half2_rn(of[f][rr*2] * inv, of[f][rr*2+1] * inv);
            *(__half2*)&g_Oh[row*DD + col] = hv;
        }
    }
}

// ---------------------------------------------------------------------------
// Launch. Inputs: 0=x, 1=mask, 2=Wq, 3=Wk, 4=Wv, 5=Wo, 6=S_q, 7=S_k
// Order: weff(1), cvt(2), Vgemm(3), QKgemm(4), attn(5), outgemm(6).
// ---------------------------------------------------------------------------
extern "C" void kernel_launch(void* const* d_in, const int* in_sizes, int n_in,
                              void* d_out, int out_size)
{
    const float* x  = (const float*)d_in[0];
    const float* Wq = (const float*)d_in[2];
    const float* Wk = (const float*)d_in[3];
    const float* Wv = (const float*)d_in[4];
    const float* Wo = (const float*)d_in[5];
    const float* Sq = (const float*)d_in[6];
    const float* Sk = (const float*)d_in[7];
    float* outp = (float*)d_out;

    __nv_bfloat16 *dA2, *dWQ2, *dWK2;
    __half *dAh, *dOh, *dWVh, *dWOh;
    cudaGetSymbolAddress((void**)&dA2,  g_A2);
    cudaGetSymbolAddress((void**)&dAh,  g_Ah);
    cudaGetSymbolAddress((void**)&dOh,  g_Oh);
    cudaGetSymbolAddress((void**)&dWQ2, g_WQ2);
    cudaGetSymbolAddress((void**)&dWK2, g_WK2);
    cudaGetSymbolAddress((void**)&dWVh, g_WVh);
    cudaGetSymbolAddress((void**)&dWOh, g_WOh);

    cudaFuncSetAttribute(gemm_qk_kernel,     cudaFuncAttributeMaxDynamicSharedMemorySize, Q4_SMEM);
    cudaFuncSetAttribute(gemm_f16_kernel<0>, cudaFuncAttributeMaxDynamicSharedMemorySize, F4_SMEM);
    cudaFuncSetAttribute(gemm_f16_kernel<1>, cudaFuncAttributeMaxDynamicSharedMemorySize, F4_SMEM);
    cudaFuncSetAttribute(attn_mma_kernel,    cudaFuncAttributeMaxDynamicSharedMemorySize, A_SMEM);

    // 1) weight prep (separate — keeps cvt low-reg)
    weff_all_kernel<<<dim3(DD/256, HH, 4), 256>>>(Wq, Wk, Wv, Wo, Sq, Sk);

    // 2) split + f16 copy of x
    cvt_split_kernel<<<(MM*DD)/256, 256>>>(x);

    // 3) V projection (1-term f16, 4 CTAs/SM) -> g_Vt transposed
    gemm_f16_kernel<1><<<dim3(16, MM/128), 128, F4_SMEM>>>(dAh, dWVh, nullptr);

    // 4) Q/K projections (3-term bf16, 4 CTAs/SM)
    const float qscale = 0.125f * 1.4426950408889634f;   // scale * log2(e)
    gemm_qk_kernel<<<dim3(32, MM/128), 128, Q4_SMEM>>>(dA2, dWQ2, dWK2, qscale);

    // 5) flash attention (64q CTAs, 3/SM) -> g_Oh f16
    attn_mma_kernel<<<dim3(TT/64, BH), 128, A_SMEM>>>();

    // 6) output projection (1-term f16, 4 CTAs/SM) -> d_out fp32
    gemm_f16_kernel<0><<<dim3(16, MM/128), 128, F4_SMEM>>>(dOh, dWOh, outp);
}